// round 16
// baseline (speedup 1.0000x reference)
#include <cuda_runtime.h>
#include <math.h>

#define NNODES 50000
#define NEDGES 800000
#define NAUG   (NEDGES + NNODES)   // edges + self loops
#define H0 25088                   // split point (divisible by 128 and 8)
#define H1 (NNODES - H0)           // 24912

// ---------------- scratch (device globals; no allocation allowed) ----------------
__device__ float g_xh  [(size_t)NNODES * 256];
__device__ float g_x2  [(size_t)NNODES * 256];
__device__ float g_ne  [(size_t)NNODES * 16];
__device__ float g_asrc[NNODES * 4];
__device__ float g_adst[NNODES * 4];
__device__ int   g_deg   [NNODES];
__device__ int   g_rowptr[NNODES + 1];
__device__ int   g_cursor[NNODES];
__device__ int   g_einc  [NAUG];
__device__ float g_F1[128 * 256];
__device__ float g_F2[16 * 256];
__device__ float g_cv[256];

// ---------------- helpers ----------------
__device__ __forceinline__ float lrelu(float x) { return x > 0.f ? x : 0.2f * x; }

__device__ __forceinline__ void ffma2(unsigned long long& d, unsigned long long a,
                                      unsigned long long b) {
    asm("fma.rn.f32x2 %0, %1, %2, %0;" : "+l"(d) : "l"(a), "l"(b));
}
__device__ __forceinline__ unsigned long long pack2(float lo, float hi) {
    unsigned long long v;
    asm("mov.b64 %0, {%1, %2};" : "=l"(v) : "r"(__float_as_uint(lo)), "r"(__float_as_uint(hi)));
    return v;
}
__device__ __forceinline__ void unpack2(unsigned long long v, float& lo, float& hi) {
    unsigned int a, b;
    asm("mov.b64 {%0, %1}, %2;" : "=r"(a), "=r"(b) : "l"(v));
    lo = __uint_as_float(a); hi = __uint_as_float(b);
}

// ---------------- zero kernel ----------------
__global__ void zero_init_kernel() {
    size_t i = (size_t)blockIdx.x * blockDim.x + threadIdx.x;
    if (i < (size_t)NNODES * 16) g_ne[i] = 0.f;
    if (i < NNODES) g_deg[i] = 0;
}

// ---------------- single-buffered f32x2 SGEMM, BK=32 (frozen R15 kernel) ----------------
#define BM 128
#define BK 32
#define TM 8
__global__ __launch_bounds__(256) void sgemm_bias(
    const float* __restrict__ A, const float* __restrict__ B,
    const float* __restrict__ bias, float* __restrict__ C,
    int M, int K)
{
    __shared__ float As[BK][BM];
    __shared__ float Bs[BK][BM];
    int tid  = threadIdx.x;
    int brow = blockIdx.y, bcol = blockIdx.x;
    int trow = (tid / 16) * TM;
    int n0   = (tid % 16) * 4;
    int arow = tid >> 1;
    int acol = (tid & 1) * 16;
    int browi = tid >> 5;
    int bcoli = (tid & 31) * 4;

    const float* Ablk = A + (size_t)(brow * BM) * K;
    const float* Bblk = B + bcol * 128;
    unsigned long long acc2[TM][4] = {};
    int grow_a = brow * BM + arow;

    for (int k0 = 0; k0 < K; k0 += BK) {
        #pragma unroll
        for (int c = 0; c < 4; c++) {
            float4 av = make_float4(0.f, 0.f, 0.f, 0.f);
            if (grow_a < M)
                av = *(const float4*)(Ablk + (size_t)arow * K + k0 + acol + c * 4);
            As[acol + c * 4 + 0][arow] = av.x;
            As[acol + c * 4 + 1][arow] = av.y;
            As[acol + c * 4 + 2][arow] = av.z;
            As[acol + c * 4 + 3][arow] = av.w;
        }
        #pragma unroll
        for (int c = 0; c < 4; c++) {
            float4 bv = *(const float4*)(Bblk + (size_t)(k0 + browi + c * 8) * 256 + bcoli);
            *(float4*)&Bs[browi + c * 8][bcoli] = bv;
        }
        __syncthreads();
        #pragma unroll
        for (int kk = 0; kk < BK; kk++) {
            float4 ra0 = *(const float4*)&As[kk][trow];
            float4 ra1 = *(const float4*)&As[kk][trow + 4];
            float ra[TM] = {ra0.x, ra0.y, ra0.z, ra0.w, ra1.x, ra1.y, ra1.z, ra1.w};
            ulonglong2 w0 = *(const ulonglong2*)&Bs[kk][n0];
            ulonglong2 w1 = *(const ulonglong2*)&Bs[kk][n0 + 64];
            unsigned long long rb2[4] = {w0.x, w0.y, w1.x, w1.y};
            #pragma unroll
            for (int i = 0; i < TM; i++) {
                unsigned long long a2 = pack2(ra[i], ra[i]);
                #pragma unroll
                for (int j = 0; j < 4; j++) ffma2(acc2[i][j], a2, rb2[j]);
            }
        }
        __syncthreads();
    }
    #pragma unroll
    for (int i = 0; i < TM; i++) {
        int gr = brow * BM + trow + i;
        if (gr >= M) break;
        float accf[8];
        #pragma unroll
        for (int j = 0; j < 4; j++) unpack2(acc2[i][j], accf[2 * j], accf[2 * j + 1]);
        float* crow = C + (size_t)gr * 256;
        #pragma unroll
        for (int half = 0; half < 2; half++) {
            int gc = bcol * 128 + n0 + half * 64;
            float4 v;
            v.x = accf[half * 4 + 0] + (bias ? bias[gc + 0] : 0.f);
            v.y = accf[half * 4 + 1] + (bias ? bias[gc + 1] : 0.f);
            v.z = accf[half * 4 + 2] + (bias ? bias[gc + 2] : 0.f);
            v.w = accf[half * 4 + 3] + (bias ? bias[gc + 3] : 0.f);
            *(float4*)(crow + gc) = v;
        }
    }
}

// ---------------- merged weight-fusion precompute (F1 | F2 | cvec) ----------------
__global__ __launch_bounds__(256) void fuse_all_kernel(
    const float* __restrict__ Wnp, const float* __restrict__ Wep,
    const float* __restrict__ bnp, const float* __restrict__ bep,
    const float* __restrict__ Wg1,
    float* __restrict__ F1, float* __restrict__ F2)
{
    int b = blockIdx.x, tid = threadIdx.x;
    if (b < 144) {
        __shared__ float sw[256];
        const float* Wl = (b < 128) ? (Wnp + b * 256) : (Wep + (b - 128) * 256);
        const float* Wg = (b < 128) ? Wg1 : (Wg1 + 256 * 256);
        float* out = (b < 128) ? (F1 + b * 256) : (F2 + (b - 128) * 256);
        sw[tid] = Wl[tid];
        __syncthreads();
        float acc = 0.f;
        #pragma unroll 8
        for (int j = 0; j < 256; j++) acc += sw[j] * __ldg(&Wg[j * 256 + tid]);
        out[tid] = acc;
    } else {
        float acc = 0.f;
        #pragma unroll 8
        for (int j = 0; j < 256; j++) acc += __ldg(&bnp[j]) * __ldg(&Wg1[j * 256 + tid]);
        #pragma unroll 8
        for (int j = 0; j < 256; j++) acc += __ldg(&bep[j]) * __ldg(&Wg1[(256 + j) * 256 + tid]);
        g_cv[tid] = acc;
    }
}

// ---------------- fused scatter-sum + degree histogram ----------------
__global__ void edge_mean_kernel(const float* __restrict__ ea, const int* __restrict__ ei) {
    int i = blockIdx.x * blockDim.x + threadIdx.x;
    if (i >= NEDGES * 16) return;
    int e = i >> 4, k = i & 15;
    int d = ei[NEDGES + e];
    atomicAdd(&g_ne[(size_t)d * 16 + k], ea[i]);
    if (k == 0) atomicAdd(&g_deg[d], 1);
}

// ---------------- CSR scan (deg + 1 self-loop implicit) ----------------
#define SCAN_T 1024
__global__ __launch_bounds__(SCAN_T) void scan_kernel() {
    __shared__ int part[SCAN_T];
    int t = threadIdx.x;
    const int CH = (NNODES + SCAN_T - 1) / SCAN_T;
    int base = t * CH;
    int sum = 0;
    for (int i = 0; i < CH; i++) {
        int idx = base + i;
        if (idx < NNODES) sum += g_deg[idx] + 1;
    }
    part[t] = sum;
    __syncthreads();
    for (int off = 1; off < SCAN_T; off <<= 1) {
        int v = (t >= off) ? part[t - off] : 0;
        __syncthreads();
        part[t] += v;
        __syncthreads();
    }
    int run = part[t] - sum;
    for (int i = 0; i < CH; i++) {
        int idx = base + i;
        if (idx < NNODES) {
            g_rowptr[idx] = run;
            g_cursor[idx] = run;
            run += g_deg[idx] + 1;
        }
    }
    if (t == SCAN_T - 1) g_rowptr[NNODES] = NAUG;
}

__global__ void scatter_kernel(const int* __restrict__ ei) {
    int e = blockIdx.x * blockDim.x + threadIdx.x;
    if (e >= NAUG) return;
    int s, d;
    if (e < NEDGES) { s = ei[e]; d = ei[NEDGES + e]; }
    else            { s = d = e - NEDGES; }
    int pos = atomicAdd(&g_cursor[d], 1);
    g_einc[pos] = s;
}

// ---------------- rank-16 update: xh += nefmean @ F2 + cvec ----------------
#define NPB 8
__global__ __launch_bounds__(256) void rank16_kernel() {
    __shared__ float sF2[16 * 256];
    __shared__ float sne[NPB * 16];
    int tid = threadIdx.x;
    int nb = blockIdx.x * NPB;
    #pragma unroll
    for (int i = 0; i < 16; i++) sF2[i * 256 + tid] = g_F2[i * 256 + tid];
    if (tid < NPB * 16) {
        int node = nb + tid / 16, k = tid & 15;
        int cnt = g_rowptr[node + 1] - g_rowptr[node] - 1;
        float c = cnt < 1 ? 1.f : (float)cnt;
        sne[tid] = g_ne[(size_t)node * 16 + k] / c;
    }
    __syncthreads();
    float cv = g_cv[tid];
    #pragma unroll
    for (int i = 0; i < NPB; i++) {
        int node = nb + i;
        float acc = cv;
        #pragma unroll
        for (int k = 0; k < 16; k++) acc += sne[i * 16 + k] * sF2[k * 256 + tid];
        g_xh[(size_t)node * 256 + tid] += acc;
    }
}

// ---------------- attention: warp per node, float4 loads (row-ranged) ----------------
__global__ void att_kernel(const float* __restrict__ as, const float* __restrict__ ad,
                           int off, int count) {
    int w = (blockIdx.x * blockDim.x + threadIdx.x) >> 5;
    int lane = threadIdx.x & 31;
    if (w >= count) return;
    int node = w + off;
    const float4* xr = (const float4*)(g_xh + (size_t)node * 256);
    float4 x0 = xr[lane * 2], x1 = xr[lane * 2 + 1];
    const float4* asp = (const float4*)as;
    const float4* adp = (const float4*)ad;
    float4 a0 = __ldg(&asp[lane * 2]), a1 = __ldg(&asp[lane * 2 + 1]);
    float4 d0 = __ldg(&adp[lane * 2]), d1 = __ldg(&adp[lane * 2 + 1]);
    float s1 = x0.x * a0.x + x0.y * a0.y + x0.z * a0.z + x0.w * a0.w
             + x1.x * a1.x + x1.y * a1.y + x1.z * a1.z + x1.w * a1.w;
    float s2 = x0.x * d0.x + x0.y * d0.y + x0.z * d0.z + x0.w * d0.w
             + x1.x * d1.x + x1.y * d1.y + x1.z * d1.z + x1.w * d1.w;
    #pragma unroll
    for (int o = 4; o >= 1; o >>= 1) {
        s1 += __shfl_down_sync(0xffffffffu, s1, o);
        s2 += __shfl_down_sync(0xffffffffu, s2, o);
    }
    if ((lane & 7) == 0) {
        int h = lane >> 3;
        g_asrc[node * 4 + h] = s1;
        g_adst[node * 4 + h] = s2;
    }
}

// ---------------- fused GAT: warp softmax + smem alpha + 4-wide gather (row-ranged) ----------------
#define GNB 8
#define GCAP 96
__global__ __launch_bounds__(256) void gat_fused(const float* __restrict__ bias,
                                                 float* __restrict__ out, int off) {
    __shared__ float salpha[GNB][GCAP * 4];
    __shared__ int   ssrc  [GNB][GCAP];
    __shared__ float sM[GNB][4], sDinv[GNB][4], sAdst[GNB][4];
    __shared__ int   sbeg[GNB], sdeg[GNB];

    int tid = threadIdx.x, wid = tid >> 5, lane = tid & 31;
    int node0 = blockIdx.x * GNB + off;

    {
        int node = node0 + wid;
        int beg = g_rowptr[node], end = g_rowptr[node + 1];
        int deg = end - beg;
        if (lane == 0) { sbeg[wid] = beg; sdeg[wid] = deg; }
        int h = lane & 3, slot = lane >> 2;
        float adst = g_adst[node * 4 + h];
        if (lane < 4) sAdst[wid][lane] = g_adst[node * 4 + lane];
        float m = -INFINITY, dsum = 0.f;
        for (int i = slot; i < deg; i += 8) {
            int s = g_einc[beg + i];
            float l = lrelu(g_asrc[s * 4 + h] + adst);
            if (l > m) { dsum = dsum * __expf(m - l) + 1.f; m = l; }
            else       { dsum += __expf(l - m); }
        }
        #pragma unroll
        for (int o = 16; o >= 4; o >>= 1) {
            float mo = __shfl_xor_sync(0xffffffffu, m, o);
            float d2 = __shfl_xor_sync(0xffffffffu, dsum, o);
            float M = fmaxf(m, mo);
            if (M == -INFINITY) { dsum = 0.f; }
            else dsum = dsum * __expf(m - M) + d2 * __expf(mo - M);
            m = M;
        }
        float Dinv = 1.f / dsum;
        if (lane < 4) { sM[wid][lane] = m; sDinv[wid][lane] = Dinv; }
        int cap = deg < GCAP ? deg : GCAP;
        for (int i = slot; i < cap; i += 8) {
            int s = g_einc[beg + i];
            if (h == 0) ssrc[wid][i] = s;
            float l = lrelu(g_asrc[s * 4 + h] + adst);
            salpha[wid][i * 4 + h] = __expf(l - m) * Dinv;
        }
    }
    __syncthreads();

    int h2 = tid >> 6;
    float bsv = bias[tid];
    for (int n = 0; n < GNB; n++) {
        int node = node0 + n;
        int deg = sdeg[n];
        int cap = deg < GCAP ? deg : GCAP;
        float acc0 = 0.f, acc1 = 0.f;
        int e = 0;
        for (; e + 4 <= cap; e += 4) {
            int s0 = ssrc[n][e + 0], s1 = ssrc[n][e + 1];
            int s2 = ssrc[n][e + 2], s3 = ssrc[n][e + 3];
            float a0 = salpha[n][(e + 0) * 4 + h2];
            float a1 = salpha[n][(e + 1) * 4 + h2];
            float a2 = salpha[n][(e + 2) * 4 + h2];
            float a3 = salpha[n][(e + 3) * 4 + h2];
            float x0 = g_xh[(size_t)s0 * 256 + tid];
            float x1 = g_xh[(size_t)s1 * 256 + tid];
            float x2 = g_xh[(size_t)s2 * 256 + tid];
            float x3 = g_xh[(size_t)s3 * 256 + tid];
            acc0 += a0 * x0; acc1 += a1 * x1;
            acc0 += a2 * x2; acc1 += a3 * x3;
        }
        for (; e < cap; e++) {
            int s0 = ssrc[n][e];
            acc0 += salpha[n][e * 4 + h2] * g_xh[(size_t)s0 * 256 + tid];
        }
        if (deg > GCAP) {
            int beg = sbeg[n];
            float M = sM[n][h2], Dinv = sDinv[n][h2], adst = sAdst[n][h2];
            for (e = GCAP; e < deg; e++) {
                int s0 = g_einc[beg + e];
                float l = lrelu(g_asrc[s0 * 4 + h2] + adst);
                acc0 += __expf(l - M) * Dinv * g_xh[(size_t)s0 * 256 + tid];
            }
        }
        float v = acc0 + acc1 + bsv;
        out[(size_t)node * 256 + tid] = v > 0.f ? v : expm1f(v);
    }
}

// ---------------- host launch (forked-stream, split-M pipelined graph) ----------------
extern "C" void kernel_launch(void* const* d_in, const int* in_sizes, int n_in,
                              void* d_out, int out_size) {
    const float* node_feats = (const float*)d_in[0];
    const float* edge_attr  = (const float*)d_in[1];
    const float* Wnp = (const float*)d_in[2];
    const float* bnp = (const float*)d_in[3];
    const float* Wep = (const float*)d_in[4];
    const float* bep = (const float*)d_in[5];
    const float* Wg1 = (const float*)d_in[6];
    const float* as1 = (const float*)d_in[7];
    const float* ad1 = (const float*)d_in[8];
    const float* bg1 = (const float*)d_in[9];
    const float* Wg2 = (const float*)d_in[10];
    const float* as2 = (const float*)d_in[11];
    const float* ad2 = (const float*)d_in[12];
    const float* bg2 = (const float*)d_in[13];
    const float* Wo  = (const float*)d_in[14];
    const float* bo  = (const float*)d_in[15];
    const int*   ei  = (const int*)d_in[16];
    float* out = (float*)d_out;

    float *pxh, *px2, *pF1, *pF2;
    cudaGetSymbolAddress((void**)&pxh, g_xh);
    cudaGetSymbolAddress((void**)&px2, g_x2);
    cudaGetSymbolAddress((void**)&pF1, g_F1);
    cudaGetSymbolAddress((void**)&pF2, g_F2);

    // side stream + events, created once (outside any capture)
    static cudaStream_t s2 = nullptr;
    static cudaEvent_t ev[8];
    if (s2 == nullptr) {
        cudaStreamCreateWithFlags(&s2, cudaStreamNonBlocking);
        for (int i = 0; i < 8; i++)
            cudaEventCreateWithFlags(&ev[i], cudaEventDisableTiming);
    }

    dim3 gg0(2, H0 / BM);         // 196 row-tiles
    dim3 gg1(2, (H1 + BM - 1) / BM);  // 195 row-tiles

    // ---- fork 1: edge/CSR chain on s2, weight fusion + GEMM1 on default ----
    cudaEventRecord(ev[0], 0);
    cudaStreamWaitEvent(s2, ev[0], 0);

    zero_init_kernel<<<((size_t)NNODES * 16 + 255) / 256, 256, 0, s2>>>();
    edge_mean_kernel<<<(NEDGES * 16 + 255) / 256, 256, 0, s2>>>(edge_attr, ei);
    scan_kernel<<<1, SCAN_T, 0, s2>>>();
    scatter_kernel<<<(NAUG + 255) / 256, 256, 0, s2>>>(ei);
    cudaEventRecord(ev[1], s2);

    fuse_all_kernel<<<145, 256>>>(Wnp, Wep, bnp, bep, Wg1, pF1, pF2);
    {
        dim3 gg(2, (NNODES + BM - 1) / BM);
        sgemm_bias<<<gg, 256>>>(node_feats, pF1, nullptr, pxh, NNODES, 128);
    }

    cudaStreamWaitEvent(0, ev[1], 0);
    rank16_kernel<<<NNODES / NPB, 256>>>();
    att_kernel<<<(NNODES * 32 + 255) / 256, 256>>>(as1, ad1, 0, NNODES);

    // ---- pipelined tail ----
    // gat1_h0 on D
    gat_fused<<<H0 / GNB, 256>>>(bg1, px2, 0);
    cudaEventRecord(ev[2], 0);

    // S2: gemm2_h0 + att2_h0 (needs px2 rows h0)
    cudaStreamWaitEvent(s2, ev[2], 0);
    sgemm_bias<<<gg0, 256, 0, s2>>>(px2, Wg2, nullptr, pxh, H0, 256);
    att_kernel<<<(H0 * 32 + 255) / 256, 256, 0, s2>>>(as2, ad2, 0, H0);
    cudaEventRecord(ev[3], s2);

    // D: gat1_h1, gemm2_h1, att2_h1
    gat_fused<<<H1 / GNB, 256>>>(bg1, px2, H0);
    sgemm_bias<<<gg1, 256>>>(px2 + (size_t)H0 * 256, Wg2, nullptr,
                             pxh + (size_t)H0 * 256, H1, 256);
    att_kernel<<<(H1 * 32 + 255) / 256, 256>>>(as2, ad2, H0, H1);

    // D: gat2_h0 (needs full xh + att2: wait s2 half)
    cudaStreamWaitEvent(0, ev[3], 0);
    gat_fused<<<H0 / GNB, 256>>>(bg2, px2, 0);
    cudaEventRecord(ev[4], 0);

    // S2: gemm3_h0 (out rows h0, needs px2 rows h0 from gat2_h0)
    cudaStreamWaitEvent(s2, ev[4], 0);
    sgemm_bias<<<gg0, 256, 0, s2>>>(px2, Wo, bo, out, H0, 256);
    cudaEventRecord(ev[5], s2);

    // D: gat2_h1, gemm3_h1
    gat_fused<<<H1 / GNB, 256>>>(bg2, px2, H0);
    sgemm_bias<<<gg1, 256>>>(px2 + (size_t)H0 * 256, Wo, bo,
                             out + (size_t)H0 * 256, H1, 256);

    // join s2 leaf back into default stream (graph capture requirement)
    cudaStreamWaitEvent(0, ev[5], 0);
}

// round 17
// speedup vs baseline: 1.0724x; 1.0724x over previous
#include <cuda_runtime.h>
#include <math.h>

#define NNODES 50000
#define NEDGES 800000
#define NAUG   (NEDGES + NNODES)   // edges + self loops

// ---------------- scratch (device globals; no allocation allowed) ----------------
__device__ float g_xh  [(size_t)NNODES * 256];
__device__ float g_x2  [(size_t)NNODES * 256];
__device__ float g_ne  [(size_t)NNODES * 16];
__device__ float g_asrc[NNODES * 4];
__device__ float g_adst[NNODES * 4];
__device__ int   g_deg   [NNODES];
__device__ int   g_rowptr[NNODES + 1];
__device__ int   g_cursor[NNODES];
__device__ int   g_einc  [NAUG];
__device__ float g_F1[128 * 256];
__device__ float g_F2[16 * 256];
__device__ float g_cv[256];

// ---------------- helpers ----------------
__device__ __forceinline__ float lrelu(float x) { return x > 0.f ? x : 0.2f * x; }

__device__ __forceinline__ void ffma2(unsigned long long& d, unsigned long long a,
                                      unsigned long long b) {
    asm("fma.rn.f32x2 %0, %1, %2, %0;" : "+l"(d) : "l"(a), "l"(b));
}
__device__ __forceinline__ unsigned long long pack2(float lo, float hi) {
    unsigned long long v;
    asm("mov.b64 %0, {%1, %2};" : "=l"(v) : "r"(__float_as_uint(lo)), "r"(__float_as_uint(hi)));
    return v;
}
__device__ __forceinline__ void unpack2(unsigned long long v, float& lo, float& hi) {
    unsigned int a, b;
    asm("mov.b64 {%0, %1}, %2;" : "=r"(a), "=r"(b) : "l"(v));
    lo = __uint_as_float(a); hi = __uint_as_float(b);
}

// ---------------- zero kernel ----------------
__global__ void zero_init_kernel() {
    size_t i = (size_t)blockIdx.x * blockDim.x + threadIdx.x;
    if (i < (size_t)NNODES * 16) g_ne[i] = 0.f;
    if (i < NNODES) g_deg[i] = 0;
}

// ---------------- single-buffered f32x2 SGEMM, BK=32 (frozen R15 kernel) ----------------
#define BM 128
#define BK 32
#define TM 8
__global__ __launch_bounds__(256) void sgemm_bias(
    const float* __restrict__ A, const float* __restrict__ B,
    const float* __restrict__ bias, float* __restrict__ C,
    int M, int K)
{
    __shared__ float As[BK][BM];
    __shared__ float Bs[BK][BM];
    int tid  = threadIdx.x;
    int brow = blockIdx.y, bcol = blockIdx.x;
    int trow = (tid / 16) * TM;
    int n0   = (tid % 16) * 4;
    int arow = tid >> 1;
    int acol = (tid & 1) * 16;
    int browi = tid >> 5;
    int bcoli = (tid & 31) * 4;

    const float* Ablk = A + (size_t)(brow * BM) * K;
    const float* Bblk = B + bcol * 128;
    unsigned long long acc2[TM][4] = {};
    int grow_a = brow * BM + arow;

    for (int k0 = 0; k0 < K; k0 += BK) {
        #pragma unroll
        for (int c = 0; c < 4; c++) {
            float4 av = make_float4(0.f, 0.f, 0.f, 0.f);
            if (grow_a < M)
                av = *(const float4*)(Ablk + (size_t)arow * K + k0 + acol + c * 4);
            As[acol + c * 4 + 0][arow] = av.x;
            As[acol + c * 4 + 1][arow] = av.y;
            As[acol + c * 4 + 2][arow] = av.z;
            As[acol + c * 4 + 3][arow] = av.w;
        }
        #pragma unroll
        for (int c = 0; c < 4; c++) {
            float4 bv = *(const float4*)(Bblk + (size_t)(k0 + browi + c * 8) * 256 + bcoli);
            *(float4*)&Bs[browi + c * 8][bcoli] = bv;
        }
        __syncthreads();
        #pragma unroll
        for (int kk = 0; kk < BK; kk++) {
            float4 ra0 = *(const float4*)&As[kk][trow];
            float4 ra1 = *(const float4*)&As[kk][trow + 4];
            float ra[TM] = {ra0.x, ra0.y, ra0.z, ra0.w, ra1.x, ra1.y, ra1.z, ra1.w};
            ulonglong2 w0 = *(const ulonglong2*)&Bs[kk][n0];
            ulonglong2 w1 = *(const ulonglong2*)&Bs[kk][n0 + 64];
            unsigned long long rb2[4] = {w0.x, w0.y, w1.x, w1.y};
            #pragma unroll
            for (int i = 0; i < TM; i++) {
                unsigned long long a2 = pack2(ra[i], ra[i]);
                #pragma unroll
                for (int j = 0; j < 4; j++) ffma2(acc2[i][j], a2, rb2[j]);
            }
        }
        __syncthreads();
    }
    #pragma unroll
    for (int i = 0; i < TM; i++) {
        int gr = brow * BM + trow + i;
        if (gr >= M) break;
        float accf[8];
        #pragma unroll
        for (int j = 0; j < 4; j++) unpack2(acc2[i][j], accf[2 * j], accf[2 * j + 1]);
        float* crow = C + (size_t)gr * 256;
        #pragma unroll
        for (int half = 0; half < 2; half++) {
            int gc = bcol * 128 + n0 + half * 64;
            float4 v;
            v.x = accf[half * 4 + 0] + (bias ? bias[gc + 0] : 0.f);
            v.y = accf[half * 4 + 1] + (bias ? bias[gc + 1] : 0.f);
            v.z = accf[half * 4 + 2] + (bias ? bias[gc + 2] : 0.f);
            v.w = accf[half * 4 + 3] + (bias ? bias[gc + 3] : 0.f);
            *(float4*)(crow + gc) = v;
        }
    }
}

// ---------------- merged weight-fusion precompute (F1 | F2 | cvec) ----------------
__global__ __launch_bounds__(256) void fuse_all_kernel(
    const float* __restrict__ Wnp, const float* __restrict__ Wep,
    const float* __restrict__ bnp, const float* __restrict__ bep,
    const float* __restrict__ Wg1,
    float* __restrict__ F1, float* __restrict__ F2)
{
    int b = blockIdx.x, tid = threadIdx.x;
    if (b < 144) {
        __shared__ float sw[256];
        const float* Wl = (b < 128) ? (Wnp + b * 256) : (Wep + (b - 128) * 256);
        const float* Wg = (b < 128) ? Wg1 : (Wg1 + 256 * 256);
        float* out = (b < 128) ? (F1 + b * 256) : (F2 + (b - 128) * 256);
        sw[tid] = Wl[tid];
        __syncthreads();
        float acc = 0.f;
        #pragma unroll 8
        for (int j = 0; j < 256; j++) acc += sw[j] * __ldg(&Wg[j * 256 + tid]);
        out[tid] = acc;
    } else {
        float acc = 0.f;
        #pragma unroll 8
        for (int j = 0; j < 256; j++) acc += __ldg(&bnp[j]) * __ldg(&Wg1[j * 256 + tid]);
        #pragma unroll 8
        for (int j = 0; j < 256; j++) acc += __ldg(&bep[j]) * __ldg(&Wg1[(256 + j) * 256 + tid]);
        g_cv[tid] = acc;
    }
}

// ---------------- fused scatter-sum + degree histogram ----------------
__global__ void edge_mean_kernel(const float* __restrict__ ea, const int* __restrict__ ei) {
    int i = blockIdx.x * blockDim.x + threadIdx.x;
    if (i >= NEDGES * 16) return;
    int e = i >> 4, k = i & 15;
    int d = ei[NEDGES + e];
    atomicAdd(&g_ne[(size_t)d * 16 + k], ea[i]);
    if (k == 0) atomicAdd(&g_deg[d], 1);
}

// ---------------- CSR scan (deg + 1 self-loop implicit) ----------------
#define SCAN_T 1024
__global__ __launch_bounds__(SCAN_T) void scan_kernel() {
    __shared__ int part[SCAN_T];
    int t = threadIdx.x;
    const int CH = (NNODES + SCAN_T - 1) / SCAN_T;
    int base = t * CH;
    int sum = 0;
    for (int i = 0; i < CH; i++) {
        int idx = base + i;
        if (idx < NNODES) sum += g_deg[idx] + 1;
    }
    part[t] = sum;
    __syncthreads();
    for (int off = 1; off < SCAN_T; off <<= 1) {
        int v = (t >= off) ? part[t - off] : 0;
        __syncthreads();
        part[t] += v;
        __syncthreads();
    }
    int run = part[t] - sum;
    for (int i = 0; i < CH; i++) {
        int idx = base + i;
        if (idx < NNODES) {
            g_rowptr[idx] = run;
            g_cursor[idx] = run;
            run += g_deg[idx] + 1;
        }
    }
    if (t == SCAN_T - 1) g_rowptr[NNODES] = NAUG;
}

__global__ void scatter_kernel(const int* __restrict__ ei) {
    int e = blockIdx.x * blockDim.x + threadIdx.x;
    if (e >= NAUG) return;
    int s, d;
    if (e < NEDGES) { s = ei[e]; d = ei[NEDGES + e]; }
    else            { s = d = e - NEDGES; }
    int pos = atomicAdd(&g_cursor[d], 1);
    g_einc[pos] = s;
}

// ---------------- rank-16 update: xh += nefmean @ F2 + cvec ----------------
#define NPB 8
__global__ __launch_bounds__(256) void rank16_kernel() {
    __shared__ float sF2[16 * 256];
    __shared__ float sne[NPB * 16];
    int tid = threadIdx.x;
    int nb = blockIdx.x * NPB;
    #pragma unroll
    for (int i = 0; i < 16; i++) sF2[i * 256 + tid] = g_F2[i * 256 + tid];
    if (tid < NPB * 16) {
        int node = nb + tid / 16, k = tid & 15;
        int cnt = g_rowptr[node + 1] - g_rowptr[node] - 1;
        float c = cnt < 1 ? 1.f : (float)cnt;
        sne[tid] = g_ne[(size_t)node * 16 + k] / c;
    }
    __syncthreads();
    float cv = g_cv[tid];
    #pragma unroll
    for (int i = 0; i < NPB; i++) {
        int node = nb + i;
        float acc = cv;
        #pragma unroll
        for (int k = 0; k < 16; k++) acc += sne[i * 16 + k] * sF2[k * 256 + tid];
        g_xh[(size_t)node * 256 + tid] += acc;
    }
}

// ---------------- attention: warp per node, float4 loads ----------------
__global__ void att_kernel(const float* __restrict__ as, const float* __restrict__ ad) {
    int w = (blockIdx.x * blockDim.x + threadIdx.x) >> 5;   // node
    int lane = threadIdx.x & 31;
    if (w >= NNODES) return;
    const float4* xr = (const float4*)(g_xh + (size_t)w * 256);
    float4 x0 = xr[lane * 2], x1 = xr[lane * 2 + 1];
    const float4* asp = (const float4*)as;
    const float4* adp = (const float4*)ad;
    float4 a0 = __ldg(&asp[lane * 2]), a1 = __ldg(&asp[lane * 2 + 1]);
    float4 d0 = __ldg(&adp[lane * 2]), d1 = __ldg(&adp[lane * 2 + 1]);
    float s1 = x0.x * a0.x + x0.y * a0.y + x0.z * a0.z + x0.w * a0.w
             + x1.x * a1.x + x1.y * a1.y + x1.z * a1.z + x1.w * a1.w;
    float s2 = x0.x * d0.x + x0.y * d0.y + x0.z * d0.z + x0.w * d0.w
             + x1.x * d1.x + x1.y * d1.y + x1.z * d1.z + x1.w * d1.w;
    #pragma unroll
    for (int o = 4; o >= 1; o >>= 1) {
        s1 += __shfl_down_sync(0xffffffffu, s1, o);
        s2 += __shfl_down_sync(0xffffffffu, s2, o);
    }
    if ((lane & 7) == 0) {
        int h = lane >> 3;
        g_asrc[w * 4 + h] = s1;
        g_adst[w * 4 + h] = s2;
    }
}

// ---------------- fused GAT: warp softmax + smem alpha + 4-wide gather ----------------
#define GNB 8
#define GCAP 96
__global__ __launch_bounds__(256) void gat_fused(const float* __restrict__ bias,
                                                 float* __restrict__ out) {
    __shared__ float salpha[GNB][GCAP * 4];
    __shared__ int   ssrc  [GNB][GCAP];
    __shared__ float sM[GNB][4], sDinv[GNB][4], sAdst[GNB][4];
    __shared__ int   sbeg[GNB], sdeg[GNB];

    int tid = threadIdx.x, wid = tid >> 5, lane = tid & 31;
    int node0 = blockIdx.x * GNB;

    {
        int node = node0 + wid;
        int beg = g_rowptr[node], end = g_rowptr[node + 1];
        int deg = end - beg;
        if (lane == 0) { sbeg[wid] = beg; sdeg[wid] = deg; }
        int h = lane & 3, slot = lane >> 2;
        float adst = g_adst[node * 4 + h];
        if (lane < 4) sAdst[wid][lane] = g_adst[node * 4 + lane];
        float m = -INFINITY, dsum = 0.f;
        for (int i = slot; i < deg; i += 8) {
            int s = g_einc[beg + i];
            float l = lrelu(g_asrc[s * 4 + h] + adst);
            if (l > m) { dsum = dsum * __expf(m - l) + 1.f; m = l; }
            else       { dsum += __expf(l - m); }
        }
        #pragma unroll
        for (int o = 16; o >= 4; o >>= 1) {
            float mo = __shfl_xor_sync(0xffffffffu, m, o);
            float d2 = __shfl_xor_sync(0xffffffffu, dsum, o);
            float M = fmaxf(m, mo);
            if (M == -INFINITY) { dsum = 0.f; }
            else dsum = dsum * __expf(m - M) + d2 * __expf(mo - M);
            m = M;
        }
        float Dinv = 1.f / dsum;
        if (lane < 4) { sM[wid][lane] = m; sDinv[wid][lane] = Dinv; }
        int cap = deg < GCAP ? deg : GCAP;
        for (int i = slot; i < cap; i += 8) {
            int s = g_einc[beg + i];
            if (h == 0) ssrc[wid][i] = s;
            float l = lrelu(g_asrc[s * 4 + h] + adst);
            salpha[wid][i * 4 + h] = __expf(l - m) * Dinv;
        }
    }
    __syncthreads();

    int h2 = tid >> 6;
    float bsv = bias[tid];
    for (int n = 0; n < GNB; n++) {
        int node = node0 + n;
        int deg = sdeg[n];
        int cap = deg < GCAP ? deg : GCAP;
        float acc0 = 0.f, acc1 = 0.f;
        int e = 0;
        for (; e + 4 <= cap; e += 4) {
            int s0 = ssrc[n][e + 0], s1 = ssrc[n][e + 1];
            int s2 = ssrc[n][e + 2], s3 = ssrc[n][e + 3];
            float a0 = salpha[n][(e + 0) * 4 + h2];
            float a1 = salpha[n][(e + 1) * 4 + h2];
            float a2 = salpha[n][(e + 2) * 4 + h2];
            float a3 = salpha[n][(e + 3) * 4 + h2];
            float x0 = g_xh[(size_t)s0 * 256 + tid];
            float x1 = g_xh[(size_t)s1 * 256 + tid];
            float x2 = g_xh[(size_t)s2 * 256 + tid];
            float x3 = g_xh[(size_t)s3 * 256 + tid];
            acc0 += a0 * x0; acc1 += a1 * x1;
            acc0 += a2 * x2; acc1 += a3 * x3;
        }
        for (; e < cap; e++) {
            int s0 = ssrc[n][e];
            acc0 += salpha[n][e * 4 + h2] * g_xh[(size_t)s0 * 256 + tid];
        }
        if (deg > GCAP) {
            int beg = sbeg[n];
            float M = sM[n][h2], Dinv = sDinv[n][h2], adst = sAdst[n][h2];
            for (e = GCAP; e < deg; e++) {
                int s0 = g_einc[beg + e];
                float l = lrelu(g_asrc[s0 * 4 + h2] + adst);
                acc0 += __expf(l - M) * Dinv * g_xh[(size_t)s0 * 256 + tid];
            }
        }
        float v = acc0 + acc1 + bsv;
        out[(size_t)node * 256 + tid] = v > 0.f ? v : expm1f(v);
    }
}

// ---------------- host launch (forked-stream graph, split join) ----------------
extern "C" void kernel_launch(void* const* d_in, const int* in_sizes, int n_in,
                              void* d_out, int out_size) {
    const float* node_feats = (const float*)d_in[0];
    const float* edge_attr  = (const float*)d_in[1];
    const float* Wnp = (const float*)d_in[2];
    const float* bnp = (const float*)d_in[3];
    const float* Wep = (const float*)d_in[4];
    const float* bep = (const float*)d_in[5];
    const float* Wg1 = (const float*)d_in[6];
    const float* as1 = (const float*)d_in[7];
    const float* ad1 = (const float*)d_in[8];
    const float* bg1 = (const float*)d_in[9];
    const float* Wg2 = (const float*)d_in[10];
    const float* as2 = (const float*)d_in[11];
    const float* ad2 = (const float*)d_in[12];
    const float* bg2 = (const float*)d_in[13];
    const float* Wo  = (const float*)d_in[14];
    const float* bo  = (const float*)d_in[15];
    const int*   ei  = (const int*)d_in[16];
    float* out = (float*)d_out;

    float *pxh, *px2, *pF1, *pF2;
    cudaGetSymbolAddress((void**)&pxh, g_xh);
    cudaGetSymbolAddress((void**)&px2, g_x2);
    cudaGetSymbolAddress((void**)&pF1, g_F1);
    cudaGetSymbolAddress((void**)&pF2, g_F2);

    // side stream + events, created once (outside any capture)
    static cudaStream_t s2 = nullptr;
    static cudaEvent_t evFork = nullptr, evScan = nullptr, evScatter = nullptr;
    if (s2 == nullptr) {
        cudaStreamCreateWithFlags(&s2, cudaStreamNonBlocking);
        cudaEventCreateWithFlags(&evFork, cudaEventDisableTiming);
        cudaEventCreateWithFlags(&evScan, cudaEventDisableTiming);
        cudaEventCreateWithFlags(&evScatter, cudaEventDisableTiming);
    }

    dim3 gg(2, (NNODES + BM - 1) / BM);

    // fork: side stream runs the edge/CSR chain
    cudaEventRecord(evFork, 0);
    cudaStreamWaitEvent(s2, evFork, 0);

    // --- branch S2: zero + edge sums + scan, then scatter (atomic/L2-bound) ---
    zero_init_kernel<<<((size_t)NNODES * 16 + 255) / 256, 256, 0, s2>>>();
    edge_mean_kernel<<<(NEDGES * 16 + 255) / 256, 256, 0, s2>>>(edge_attr, ei);
    scan_kernel<<<1, SCAN_T, 0, s2>>>();
    cudaEventRecord(evScan, s2);           // rank16 only needs ne + rowptr
    scatter_kernel<<<(NAUG + 255) / 256, 256, 0, s2>>>(ei);
    cudaEventRecord(evScatter, s2);        // gat_fused needs einc

    // --- branch default: weight fusion + main GEMM (fma-bound) ---
    fuse_all_kernel<<<145, 256>>>(Wnp, Wep, bnp, bep, Wg1, pF1, pF2);
    sgemm_bias<<<gg, 256>>>(node_feats, pF1, nullptr, pxh, NNODES, 128);

    // join 1: rank16 (scatter still running on s2 underneath)
    cudaStreamWaitEvent(0, evScan, 0);
    rank16_kernel<<<NNODES / NPB, 256>>>();
    att_kernel<<<(NNODES * 32 + 255) / 256, 256>>>(as1, ad1);

    // join 2: gat needs the CSR column list
    cudaStreamWaitEvent(0, evScatter, 0);
    gat_fused<<<NNODES / GNB, 256>>>(bg1, px2);

    // GAT layer 2
    sgemm_bias<<<gg, 256>>>(px2, Wg2, nullptr, pxh, NNODES, 256);
    att_kernel<<<(NNODES * 32 + 255) / 256, 256>>>(as2, ad2);
    gat_fused<<<NNODES / GNB, 256>>>(bg2, px2);

    // output projection -> d_out
    sgemm_bias<<<gg, 256>>>(px2, Wo, bo, out, NNODES, 256);
}